// round 16
// baseline (speedup 1.0000x reference)
#include <cuda_runtime.h>
#include <math.h>

// Problem constants (fixed by the reference setup_inputs)
#define BB 1
#define VV 3
#define CC 32
#define DD 48
#define HH 128
#define WW 160
#define HW (HH*WW)
#define DHW ((size_t)DD*HW)

#define RS 29              // s27 row stride (29 odd -> conflict-free)
#define BS 36              // buf row stride (16B-aligned, conflict-free LDS.128)
#define CPS 52             // cost smem stride (16B-aligned float4 rows)

// Scratch (static device globals — no runtime allocation)
__device__ float g_featT[VV * HW * CC];            // (v, h, w, c)    7.9 MB
__device__ float g_t[9 * DHW];                     // (tap9, z, y, x) 35.4 MB
__device__ float g_rt[(VV - 1) * 12];              // per src view: rot[9], trans[3]

// ---------------------------------------------------------------------------
// packed f32x2 helpers
// ---------------------------------------------------------------------------
__device__ __forceinline__ unsigned long long pk(float lo, float hi) {
    unsigned long long r;
    asm("mov.b64 %0,{%1,%2};" : "=l"(r) : "f"(lo), "f"(hi));
    return r;
}
__device__ __forceinline__ void upk(unsigned long long v, float& lo, float& hi) {
    asm("mov.b64 {%0,%1},%2;" : "=f"(lo), "=f"(hi) : "l"(v));
}
__device__ __forceinline__ unsigned long long mul2(unsigned long long a, unsigned long long b) {
    unsigned long long d;
    asm("mul.rn.f32x2 %0,%1,%2;" : "=l"(d) : "l"(a), "l"(b));
    return d;
}
__device__ __forceinline__ unsigned long long add2(unsigned long long a, unsigned long long b) {
    unsigned long long d;
    asm("add.rn.f32x2 %0,%1,%2;" : "=l"(d) : "l"(a), "l"(b));
    return d;
}
__device__ __forceinline__ unsigned long long fma2(unsigned long long a, unsigned long long b,
                                                   unsigned long long c) {
    unsigned long long d;
    asm("fma.rn.f32x2 %0,%1,%2,%3;" : "=l"(d) : "l"(a), "l"(b), "l"(c));
    return d;
}

// ---------------------------------------------------------------------------
// Kernel 0: rot/trans = src_proj @ inv(ref_proj)  (cofactor inverse, 1 thread)
// ---------------------------------------------------------------------------
__global__ void k_setup(const float* __restrict__ proj) {
    if (threadIdx.x != 0 || blockIdx.x != 0) return;
    double m[16], inv[16];
    for (int i = 0; i < 16; i++) m[i] = (double)proj[i];   // ref_proj (b=0,v=0)

    inv[0]  =  m[5]*m[10]*m[15] - m[5]*m[11]*m[14] - m[9]*m[6]*m[15] + m[9]*m[7]*m[14] + m[13]*m[6]*m[11] - m[13]*m[7]*m[10];
    inv[4]  = -m[4]*m[10]*m[15] + m[4]*m[11]*m[14] + m[8]*m[6]*m[15] - m[8]*m[7]*m[14] - m[12]*m[6]*m[11] + m[12]*m[7]*m[10];
    inv[8]  =  m[4]*m[9]*m[15]  - m[4]*m[11]*m[13] - m[8]*m[5]*m[15] + m[8]*m[7]*m[13] + m[12]*m[5]*m[11] - m[12]*m[7]*m[9];
    inv[12] = -m[4]*m[9]*m[14]  + m[4]*m[10]*m[13] + m[8]*m[5]*m[14] - m[8]*m[6]*m[13] - m[12]*m[5]*m[10] + m[12]*m[6]*m[9];
    inv[1]  = -m[1]*m[10]*m[15] + m[1]*m[11]*m[14] + m[9]*m[2]*m[15] - m[9]*m[3]*m[14] - m[13]*m[2]*m[11] + m[13]*m[3]*m[10];
    inv[5]  =  m[0]*m[10]*m[15] - m[0]*m[11]*m[14] - m[8]*m[2]*m[15] + m[8]*m[3]*m[14] + m[12]*m[2]*m[11] - m[12]*m[3]*m[10];
    inv[9]  = -m[0]*m[9]*m[15]  + m[0]*m[11]*m[13] + m[8]*m[1]*m[15] - m[8]*m[3]*m[13] - m[12]*m[1]*m[11] + m[12]*m[3]*m[9];
    inv[13] =  m[0]*m[9]*m[14]  - m[0]*m[10]*m[13] - m[8]*m[1]*m[14] + m[8]*m[2]*m[13] + m[12]*m[1]*m[10] - m[12]*m[2]*m[9];
    inv[2]  =  m[1]*m[6]*m[15]  - m[1]*m[7]*m[14]  - m[5]*m[2]*m[15] + m[5]*m[3]*m[14] + m[13]*m[2]*m[7]  - m[13]*m[3]*m[6];
    inv[6]  = -m[0]*m[6]*m[15]  + m[0]*m[7]*m[14]  + m[4]*m[2]*m[15] - m[4]*m[3]*m[14] - m[12]*m[2]*m[7]  + m[12]*m[3]*m[6];
    inv[10] =  m[0]*m[5]*m[15]  - m[0]*m[7]*m[13]  - m[4]*m[1]*m[15] + m[4]*m[3]*m[13] + m[12]*m[1]*m[7]  - m[12]*m[3]*m[5];
    inv[14] = -m[0]*m[5]*m[14]  + m[0]*m[6]*m[13]  + m[4]*m[1]*m[14] - m[4]*m[2]*m[13] - m[12]*m[1]*m[6]  + m[12]*m[2]*m[5];
    inv[3]  = -m[1]*m[6]*m[11]  + m[1]*m[7]*m[10]  + m[5]*m[2]*m[11] - m[5]*m[3]*m[10] - m[9]*m[2]*m[7]   + m[9]*m[3]*m[6];
    inv[7]  =  m[0]*m[6]*m[11]  - m[0]*m[7]*m[10]  - m[4]*m[2]*m[11] + m[4]*m[3]*m[10] + m[8]*m[2]*m[7]   - m[8]*m[3]*m[6];
    inv[11] = -m[0]*m[5]*m[11]  + m[0]*m[7]*m[9]   + m[4]*m[1]*m[11] - m[4]*m[3]*m[9]  - m[8]*m[1]*m[7]   + m[8]*m[3]*m[5];
    inv[15] =  m[0]*m[5]*m[10]  - m[0]*m[6]*m[9]   - m[4]*m[1]*m[10] + m[4]*m[2]*m[9]  + m[8]*m[1]*m[6]   - m[8]*m[2]*m[5];

    double det = m[0]*inv[0] + m[1]*inv[4] + m[2]*inv[8] + m[3]*inv[12];
    double id = 1.0 / det;
    for (int i = 0; i < 16; i++) inv[i] *= id;

    for (int v = 1; v < VV; v++) {
        const float* P = proj + v * 16;
        for (int i = 0; i < 3; i++) {
            double r[4];
            for (int j = 0; j < 4; j++) {
                double s = 0.0;
                for (int k = 0; k < 4; k++) s += (double)P[i * 4 + k] * inv[k * 4 + j];
                r[j] = s;
            }
            g_rt[(v - 1) * 12 + i * 3 + 0] = (float)r[0];
            g_rt[(v - 1) * 12 + i * 3 + 1] = (float)r[1];
            g_rt[(v - 1) * 12 + i * 3 + 2] = (float)r[2];
            g_rt[(v - 1) * 12 + 9 + i]     = (float)r[3];
        }
    }
}

// ---------------------------------------------------------------------------
// Kernel 1: transpose features (v,c,h,w) -> (v,hw,c)
// ---------------------------------------------------------------------------
__global__ void k_transpose(const float* __restrict__ feat) {
    __shared__ float tile[32][33];
    int v   = blockIdx.y;
    int hw0 = blockIdx.x * 32;
    int tx = threadIdx.x, ty = threadIdx.y;
    tile[ty][tx] = feat[((size_t)v * CC + ty) * HW + hw0 + tx];
    __syncthreads();
    g_featT[(size_t)v * HW * CC + (size_t)(hw0 + ty) * CC + tx] = tile[tx][ty];
}

// ---------------------------------------------------------------------------
// Kernel 2 (fused): warp + variance + 27 channel-dots + kw-combine -> t9.
// Phase-2 smem traffic via LDS.128 (v and broadcast weights).
// ---------------------------------------------------------------------------
__global__ __launch_bounds__(160, 5) void k_vt9(const float* __restrict__ dvals,
                                                const float* __restrict__ wgt) {
    __shared__ __align__(16) float sw[27 * 32];    // [tap][c], 128B per tap row
    __shared__ __align__(16) float buf[160 * BS];  // phase1: var[x][BS]; alias: s[162][RS]

    const int tid = threadIdx.x;
    const int z = blockIdx.x;     // depth slab
    const int y = blockIdx.y;     // row
    const float dv = dvals[z];

    // weights: gmem c*27+tap -> sw[tap*32+c]
    for (int i = tid; i < 864; i += 160) {
        int c = i / 27, tap = i % 27;
        sw[tap * 32 + c] = wgt[i];
    }

    // per-view linear projection coefficients:  p(x) = A*x + B
    float Ax[2], Bx[2], Ay[2], By[2], Az[2], Bz[2];
#pragma unroll
    for (int v = 0; v < 2; v++) {
        const float* rt = g_rt + v * 12;
        float yf = (float)y;
        Ax[v] = rt[0] * dv;  Bx[v] = (rt[1] * yf + rt[2]) * dv + rt[9];
        Ay[v] = rt[3] * dv;  By[v] = (rt[4] * yf + rt[5]) * dv + rt[10];
        Az[v] = rt[6] * dv;  Bz[v] = (rt[7] * yf + rt[8]) * dv + rt[11];
    }

    const int j   = tid & 7;      // channel chunk (float4)
    const int p20 = tid >> 3;     // pixel within 20-group
    const float* f1 = g_featT + (size_t)1 * HW * CC;
    const float* f2 = g_featT + (size_t)2 * HW * CC;
    const unsigned long long IV  = pk(1.f / 3.f, 1.f / 3.f);
    const unsigned long long NIV = pk(-1.f / 3.f, -1.f / 3.f);

    // ---- phase 1: variance per (pixel, chunk) into buf ----
#pragma unroll 1
    for (int it = 0; it < 8; it++) {
        const int x = it * 20 + p20;
        const float xf = (float)x;

        float cw[2][4];
        int   co[2][4];
#pragma unroll
        for (int v = 0; v < 2; v++) {
            float pz = Az[v] * xf + Bz[v];
            float gx = (Ax[v] * xf + Bx[v]) / pz;
            float gy = (Ay[v] * xf + By[v]) / pz;
            float x0 = floorf(gx), y0 = floorf(gy);
            float fx = gx - x0, fy = gy - y0;
            float xs[2] = { x0, x0 + 1.f };
            float ys[2] = { y0, y0 + 1.f };
            float wx[2] = { 1.f - fx, fx };
            float wy[2] = { 1.f - fy, fy };
#pragma unroll
            for (int cy = 0; cy < 2; cy++)
#pragma unroll
                for (int cx = 0; cx < 2; cx++) {
                    bool valid = (xs[cx] >= 0.f) && (xs[cx] <= (float)(WW - 1)) &&
                                 (ys[cy] >= 0.f) && (ys[cy] <= (float)(HH - 1));
                    int xi = (int)fminf(fmaxf(xs[cx], 0.f), (float)(WW - 1));
                    int yi = (int)fminf(fmaxf(ys[cy], 0.f), (float)(HH - 1));
                    cw[v][cy * 2 + cx] = valid ? wx[cx] * wy[cy] : 0.f;
                    co[v][cy * 2 + cx] = (yi * WW + xi) * CC + j * 4;
                }
        }

        ulonglong2 r = *(const ulonglong2*)(g_featT + (size_t)(y * WW + x) * CC + j * 4);
        unsigned long long slo = r.x, shi = r.y;
        unsigned long long qlo = mul2(r.x, r.x), qhi = mul2(r.y, r.y);
#pragma unroll
        for (int v = 0; v < 2; v++) {
            const float* fp = (v == 0) ? f1 : f2;
            ulonglong2 a = *(const ulonglong2*)(fp + co[v][0]);
            ulonglong2 b = *(const ulonglong2*)(fp + co[v][1]);
            ulonglong2 c = *(const ulonglong2*)(fp + co[v][2]);
            ulonglong2 e = *(const ulonglong2*)(fp + co[v][3]);
            unsigned long long w0 = pk(cw[v][0], cw[v][0]);
            unsigned long long w1 = pk(cw[v][1], cw[v][1]);
            unsigned long long w2 = pk(cw[v][2], cw[v][2]);
            unsigned long long w3 = pk(cw[v][3], cw[v][3]);
            unsigned long long vlo = mul2(a.x, w0);
            vlo = fma2(b.x, w1, vlo); vlo = fma2(c.x, w2, vlo); vlo = fma2(e.x, w3, vlo);
            unsigned long long vhi = mul2(a.y, w0);
            vhi = fma2(b.y, w1, vhi); vhi = fma2(c.y, w2, vhi); vhi = fma2(e.y, w3, vhi);
            slo = add2(slo, vlo); shi = add2(shi, vhi);
            qlo = fma2(vlo, vlo, qlo); qhi = fma2(vhi, vhi, qhi);
        }
        // var = q/3 - (s/3)^2  = (-s/3)*(s/3) + q/3
        unsigned long long mlo = mul2(slo, IV),  mhi = mul2(shi, IV);
        unsigned long long nlo = mul2(slo, NIV), nhi = mul2(shi, NIV);
        ulonglong2 st;
        st.x = fma2(nlo, mlo, mul2(qlo, IV));
        st.y = fma2(nhi, mhi, mul2(qhi, IV));
        *(ulonglong2*)(buf + x * BS + j * 4) = st;      // STS.128, aligned
    }
    __syncthreads();

    // ---- phase 2: v via 8x LDS.128; weights via broadcast LDS.128 ----
    const int w = tid;
    ulonglong2 v2[8];
#pragma unroll
    for (int k = 0; k < 8; k++)
        v2[k] = *(const ulonglong2*)(buf + w * BS + k * 4);
    __syncthreads();            // everyone done reading var; buf becomes s

    float* s = buf;             // s[(x+1)*RS + tap], x in [-1, 160]
    if (tid < 2) {
        int row = (tid == 0) ? 0 : 161;
#pragma unroll
        for (int tap = 0; tap < 27; tap++) s[row * RS + tap] = 0.f;
    }
#pragma unroll 9
    for (int tap = 0; tap < 27; tap++) {
        const ulonglong2* wp = (const ulonglong2*)(sw + tap * 32);
        unsigned long long acc = 0ull;
#pragma unroll
        for (int k = 0; k < 8; k++) {
            ulonglong2 wv = wp[k];                      // broadcast LDS.128
            acc = fma2(v2[k].x, wv.x, acc);
            acc = fma2(v2[k].y, wv.y, acc);
        }
        float lo, hi; upk(acc, lo, hi);
        s[(w + 1) * RS + tap] = lo + hi;
    }
    __syncthreads();

    // ---- phase 3: kw-combine -> t9, coalesced stores ----
    const size_t base = (size_t)z * HW + y * WW + w;
#pragma unroll
    for (int kd = 0; kd < 3; kd++)
#pragma unroll
        for (int kh = 0; kh < 3; kh++) {
            int tb = kd * 9 + kh * 3;
            float t = s[w * RS + tb] + s[(w + 1) * RS + tb + 1] + s[(w + 2) * RS + tb + 2];
            g_t[(size_t)(kd * 3 + kh) * DHW + base] = t;
        }
}

// ---------------------------------------------------------------------------
// Kernel 3 (fused): t9 gather + softmax + depth regression + confidence.
// One block per h-row: phase A gathers all (d,w) points coalesced into a
// (w,d) smem tile; phase B does per-pixel softmax from smem. Full-chip
// parallel gather replaces the latency-bound 80-block k_post.
// ---------------------------------------------------------------------------
__global__ __launch_bounds__(256) void k_cost_post(const float* __restrict__ dvals,
                                                   const float* __restrict__ bias,
                                                   float* __restrict__ out) {
    __shared__ __align__(16) float sc[160 * CPS];   // [w][d] cost tile (33.3KB)
    const int tid = threadIdx.x;
    const int h = blockIdx.x;
    const float b0 = bias[0];

    // ---- phase A: cost(d, h, w) for all d,w of this row (coalesced in w) ----
#pragma unroll 1
    for (int i = 0; i < (DD * WW) / 256; i++) {
        int idx = i * 256 + tid;
        int d = idx / WW;
        int w = idx - d * WW;
        float sum = b0;
#pragma unroll
        for (int kd = 0; kd < 3; kd++) {
            int zz = d + kd - 1;
            if ((unsigned)zz >= (unsigned)DD) continue;
#pragma unroll
            for (int kh = 0; kh < 3; kh++) {
                int yy = h + kh - 1;
                if ((unsigned)yy >= (unsigned)HH) continue;
                sum += g_t[(size_t)(kd * 3 + kh) * DHW + (size_t)zz * HW + yy * WW + w];
            }
        }
        sc[w * CPS + d] = sum;
    }
    __syncthreads();

    // ---- phase B: per-pixel softmax / depth / confidence ----
    if (tid < WW) {
        const int w = tid;
        float c[DD];
#pragma unroll
        for (int k = 0; k < DD / 4; k++) {
            float4 q = *(const float4*)(sc + w * CPS + k * 4);
            c[k * 4 + 0] = q.x; c[k * 4 + 1] = q.y;
            c[k * 4 + 2] = q.z; c[k * 4 + 3] = q.w;
        }
        float m = -1e30f;
#pragma unroll
        for (int d = 0; d < DD; d++) m = fmaxf(m, c[d]);
        float se = 0.f;
#pragma unroll
        for (int d = 0; d < DD; d++) { c[d] = expf(c[d] - m); se += c[d]; }
        float inv = 1.f / se;
        float depth = 0.f, fi = 0.f;
#pragma unroll
        for (int d = 0; d < DD; d++) {
            c[d] *= inv;
            depth += c[d] * dvals[d];
            fi += c[d] * (float)d;
        }
        int di = (int)fi;
        di = min(max(di, 0), DD - 1);
        float conf = 0.f;
#pragma unroll
        for (int d = 0; d < DD; d++) {
            bool in = (d >= di - 1) && (d <= di + 2);
            conf += in ? c[d] : 0.f;
        }
        out[h * WW + w]      = depth;
        out[HW + h * WW + w] = conf;
    }
}

// ---------------------------------------------------------------------------
extern "C" void kernel_launch(void* const* d_in, const int* in_sizes, int n_in,
                              void* d_out, int out_size) {
    const float* features = (const float*)d_in[0];   // (1,3,32,128,160)
    const float* proj     = (const float*)d_in[1];   // (1,3,4,4)
    const float* dvals    = (const float*)d_in[2];   // (1,48)
    const float* rweight  = (const float*)d_in[3];   // (1,32,3,3,3)
    const float* rbias    = (const float*)d_in[4];   // (1,)
    float* out = (float*)d_out;                      // depth(20480) ++ conf(20480)

    k_setup<<<1, 32>>>(proj);
    k_transpose<<<dim3(HW / 32, VV), dim3(32, 32)>>>(features);
    k_vt9<<<dim3(DD, HH), 160>>>(dvals, rweight);
    k_cost_post<<<HH, 256>>>(dvals, rbias, out);
}